// round 1
// baseline (speedup 1.0000x reference)
#include <cuda_runtime.h>
#include <cuda_bf16.h>
#include <cstdint>

// ---------------------------------------------------------------------------
// LigEdgeBuilder: edge_attr = lig_ea + (relu(gauss(d) @ W1 + b1) @ W2 + b2)
//   d = |pos[dst] - pos[src]|, gauss = exp(coeff*(d - offsets)^2), R=50, F=64
// Strategy:
//   - tile of 64 edges per block iteration, 128 threads (4 warps)
//   - Gaussian smearing computed scalar with +-3.6 window (tail < 3e-8)
//   - both GEMMs as bf16 mma.sync.m16n8k16 (K padded 50->64), fp32 accum
//   - persistent grid-stride blocks; weights converted to bf16 smem once
// ---------------------------------------------------------------------------

#define TILE_E   64
#define THREADS  128
#define SSTRIDE  72   // bf16 elements per smem row (64 + 8 pad: conflict-free ldmatrix)

__device__ int g_idx64;   // 1 if edge_index is int64, 0 if int32 (set by detect kernel)

__device__ __forceinline__ uint32_t smem_u32(const void* p) {
    return (uint32_t)__cvta_generic_to_shared(p);
}

__device__ __forceinline__ void mma16816(float c[4], const uint32_t a[4],
                                         uint32_t b0, uint32_t b1) {
    asm volatile(
        "mma.sync.aligned.m16n8k16.row.col.f32.bf16.bf16.f32 "
        "{%0,%1,%2,%3}, {%4,%5,%6,%7}, {%8,%9}, {%0,%1,%2,%3};\n"
        : "+f"(c[0]), "+f"(c[1]), "+f"(c[2]), "+f"(c[3])
        : "r"(a[0]), "r"(a[1]), "r"(a[2]), "r"(a[3]), "r"(b0), "r"(b1));
}

// C[m0:m0+16, 0:64] += A[64,64] @ B[64,64]; A,B bf16 row-major in smem, stride SSTRIDE.
__device__ __forceinline__ void gemm64(const __nv_bfloat16* __restrict__ sA,
                                       const __nv_bfloat16* __restrict__ sB,
                                       int lane, int m0, float acc[8][4]) {
#pragma unroll
    for (int kt = 0; kt < 4; kt++) {
        uint32_t a[4];
        {
            const __nv_bfloat16* ap =
                sA + (m0 + (lane & 15)) * SSTRIDE + kt * 16 + ((lane >> 4) * 8);
            uint32_t addr = smem_u32(ap);
            asm volatile("ldmatrix.sync.aligned.m8n8.x4.shared.b16 {%0,%1,%2,%3}, [%4];\n"
                         : "=r"(a[0]), "=r"(a[1]), "=r"(a[2]), "=r"(a[3])
                         : "r"(addr));
        }
#pragma unroll
        for (int j = 0; j < 8; j += 2) {
            uint32_t b[4];
            const __nv_bfloat16* bp =
                sB + (kt * 16 + (lane & 15)) * SSTRIDE + j * 8 + ((lane >> 4) * 8);
            uint32_t addr = smem_u32(bp);
            asm volatile("ldmatrix.sync.aligned.m8n8.x4.trans.shared.b16 {%0,%1,%2,%3}, [%4];\n"
                         : "=r"(b[0]), "=r"(b[1]), "=r"(b[2]), "=r"(b[3])
                         : "r"(addr));
            mma16816(acc[j],     a, b[0], b[1]);
            mma16816(acc[j + 1], a, b[2], b[3]);
        }
    }
}

struct Smem {
    __nv_bfloat16 W1[64 * SSTRIDE];
    __nv_bfloat16 W2[64 * SSTRIDE];
    __nv_bfloat16 G [64 * SSTRIDE];
    __nv_bfloat16 H [64 * SSTRIDE];
    float b1[64];
    float b2[64];
};

__global__ void __launch_bounds__(THREADS)
lig_edge_kernel(const float* __restrict__ pos,
                const float* __restrict__ lig_ea,
                const void*  __restrict__ ei_raw,
                const float* __restrict__ W1,
                const float* __restrict__ b1,
                const float* __restrict__ W2,
                const float* __restrict__ b2,
                float* __restrict__ outAttr,
                int E, int numTiles)
{
    __shared__ Smem s;
    const int tid  = threadIdx.x;
    const int lane = tid & 31;
    const int warp = tid >> 5;
    const int m0   = warp * 16;

    const int idx64 = g_idx64;
    const long long*  ei64 = (const long long*)ei_raw;
    const int*        ei32 = (const int*)ei_raw;

    // ---- one-time weight staging (bf16, zero-padded K rows) ----
    for (int i = tid; i < 64 * SSTRIDE; i += THREADS)
        s.W1[i] = __float2bfloat16(0.0f);
    __syncthreads();
    for (int i = tid; i < 50 * 64; i += THREADS)
        s.W1[(i / 64) * SSTRIDE + (i % 64)] = __float2bfloat16(W1[i]);
    for (int i = tid; i < 64 * 64; i += THREADS)
        s.W2[(i / 64) * SSTRIDE + (i % 64)] = __float2bfloat16(W2[i]);
    if (tid < 64) { s.b1[tid] = b1[tid]; s.b2[tid] = b2[tid]; }
    // ordering vs first reads is covered by the sync after the G-fill below

    const float step  = 30.0f / 49.0f;
    const float coeff = -0.5f * (49.0f / 30.0f) * (49.0f / 30.0f);

    for (long long tile = blockIdx.x; tile < numTiles; tile += gridDim.x) {
        const long long e0 = tile * TILE_E;
        __syncthreads();   // protect G against warps still in prior GEMM1 epilogue path

        // ---- Gaussian smearing tile: G[64 edges][64] (cols 50..63 zero) ----
        {
            const int el   = tid >> 1;        // local edge 0..63
            const int half = tid & 1;         // 32-col half
            const long long e = e0 + el;
            float d = 0.0f;
            if (e < E) {
                long long srcI, dstI;
                if (idx64) { srcI = ei64[e]; dstI = ei64[(long long)E + e]; }
                else       { srcI = ei32[e]; dstI = ei32[(long long)E + e]; }
                const float* ps = pos + srcI * 3;
                const float* pd = pos + dstI * 3;
                float dx = pd[0] - ps[0];
                float dy = pd[1] - ps[1];
                float dz = pd[2] - ps[2];
                d = sqrtf(dx * dx + dy * dy + dz * dz);
            }
            __nv_bfloat16* grow = s.G + el * SSTRIDE + half * 32;
#pragma unroll 4
            for (int c = 0; c < 32; c++) {
                const int col = half * 32 + c;
                float val = 0.0f;
                if (e < E && col < 50) {
                    float t = d - col * step;
                    if (fabsf(t) < 3.6f) val = __expf(coeff * t * t);
                }
                grow[c] = __float2bfloat16(val);
            }
        }
        __syncthreads();

        // ---- GEMM1: H = relu(G @ W1 + b1) -> bf16 smem ----
        {
            float acc[8][4] = {};
            gemm64(s.G, s.W1, lane, m0, acc);
            const int r0 = m0 + (lane >> 2);
#pragma unroll
            for (int j = 0; j < 8; j++) {
                const int col = j * 8 + (lane & 3) * 2;
                float v0 = fmaxf(acc[j][0] + s.b1[col],     0.0f);
                float v1 = fmaxf(acc[j][1] + s.b1[col + 1], 0.0f);
                float v2 = fmaxf(acc[j][2] + s.b1[col],     0.0f);
                float v3 = fmaxf(acc[j][3] + s.b1[col + 1], 0.0f);
                *(__nv_bfloat162*)&s.H[r0 * SSTRIDE + col]       = __floats2bfloat162_rn(v0, v1);
                *(__nv_bfloat162*)&s.H[(r0 + 8) * SSTRIDE + col] = __floats2bfloat162_rn(v2, v3);
            }
        }
        __syncthreads();

        // ---- GEMM2: emb = H @ W2; epilogue out = lig_ea + emb + b2 ----
        {
            float acc[8][4] = {};
            gemm64(s.H, s.W2, lane, m0, acc);
            const long long er0 = e0 + m0 + (lane >> 2);
#pragma unroll
            for (int j = 0; j < 8; j++) {
                const int col = j * 8 + (lane & 3) * 2;
                const float bb0 = s.b2[col];
                const float bb1 = s.b2[col + 1];
                if (er0 < E) {
                    const float2 lg = *(const float2*)(lig_ea + er0 * 64 + col);
                    float2 o;
                    o.x = lg.x + acc[j][0] + bb0;
                    o.y = lg.y + acc[j][1] + bb1;
                    *(float2*)(outAttr + er0 * 64 + col) = o;
                }
                const long long er1 = er0 + 8;
                if (er1 < E) {
                    const float2 lg = *(const float2*)(lig_ea + er1 * 64 + col);
                    float2 o;
                    o.x = lg.x + acc[j][2] + bb0;
                    o.y = lg.y + acc[j][3] + bb1;
                    *(float2*)(outAttr + er1 * 64 + col) = o;
                }
            }
        }
    }
}

// ---- edge_index dtype detection: int32 read as int64 -> huge values ----
__global__ void detect_idx_kernel(const void* __restrict__ ei, int twoE) {
    if (threadIdx.x == 0 && blockIdx.x == 0) {
        const long long* p = (const long long*)ei;
        int n = twoE < 256 ? twoE : 256;
        int ok = 1;
        for (int i = 0; i < n; i++) {
            long long v = p[i];
            if (v < 0 || v >= (1LL << 31)) { ok = 0; break; }
        }
        g_idx64 = ok;
    }
}

__global__ void write_idx_float(const void* __restrict__ ei, float* __restrict__ out, int n) {
    int i = blockIdx.x * blockDim.x + threadIdx.x;
    if (i < n) {
        long long v = g_idx64 ? ((const long long*)ei)[i] : (long long)((const int*)ei)[i];
        out[i] = (float)v;
    }
}

__global__ void write_idx_raw(const void* __restrict__ ei, long long* __restrict__ out, int n) {
    int i = blockIdx.x * blockDim.x + threadIdx.x;
    if (i < n) {
        long long v = g_idx64 ? ((const long long*)ei)[i] : (long long)((const int*)ei)[i];
        out[i] = v;
    }
}

extern "C" void kernel_launch(void* const* d_in, const int* in_sizes, int n_in,
                              void* d_out, int out_size)
{
    // Resolve inputs by element count (robust to ordering); b1 before b2 among size-64.
    const float* pos = nullptr;
    const float* lig = nullptr;
    const void*  ei  = nullptr;
    const float* W1  = nullptr;
    const float* b1  = nullptr;
    const float* W2  = nullptr;
    const float* b2  = nullptr;

    // First pass: find lig_ea (largest) to get E.
    long long maxSz = -1; int ligIdx = -1;
    for (int i = 0; i < n_in; i++)
        if ((long long)in_sizes[i] > maxSz) { maxSz = in_sizes[i]; ligIdx = i; }
    lig = (const float*)d_in[ligIdx];
    const int E = (int)(maxSz / 64);

    for (int i = 0; i < n_in; i++) {
        long long sz = in_sizes[i];
        if (i == ligIdx) continue;
        if (sz == 50LL * 64)          W1 = (const float*)d_in[i];
        else if (sz == 64LL * 64)     W2 = (const float*)d_in[i];
        else if (sz == 64) {
            if (!b1) b1 = (const float*)d_in[i];
            else     b2 = (const float*)d_in[i];
        }
        else if (sz == 2LL * E || sz == 4LL * E) ei = d_in[i];  // edge_index (elem count may be dtype-dependent)
        else                        pos = (const float*)d_in[i]; // N_NODES*3
    }

    float* out  = (float*)d_out;
    float* attr = out;
    const long long nAttr = (long long)E * 64;

    detect_idx_kernel<<<1, 32>>>(ei, 2 * E);

    if ((long long)out_size == nAttr + 2LL * E) {
        // output = [edge_index as float32 (2E), edge_attr (E*64)]
        int n = 2 * E;
        write_idx_float<<<(n + 255) / 256, 256>>>(ei, out, n);
        attr = out + 2LL * E;
    } else if ((long long)out_size == nAttr + 4LL * E) {
        // output dtype-slots suggest raw int64 prefix (2E int64 == 4E f32 slots)
        int n = 2 * E;
        write_idx_raw<<<(n + 255) / 256, 256>>>(ei, (long long*)d_out, n);
        attr = out + 4LL * E;
    }
    // else: out_size == nAttr -> edge_attr only

    const int numTiles = (E + TILE_E - 1) / TILE_E;
    int grid = numTiles < 888 ? numTiles : 888;   // 148 SMs * 6 resident blocks
    lig_edge_kernel<<<grid, THREADS>>>(pos, lig, ei, W1, b1, W2, b2, attr, E, numTiles);
}

// round 4
// speedup vs baseline: 1.2229x; 1.2229x over previous
#include <cuda_runtime.h>
#include <cuda_bf16.h>
#include <cstdint>

// ---------------------------------------------------------------------------
// LigEdgeBuilder: edge_attr = lig_ea + (relu(gauss(d) @ W1 + b1) @ W2 + b2)
// Warp-autonomous design: each warp owns a 16-edge tile (m16 rows = edges).
//   - Gaussian A-fragments built directly in registers (no G smem, no A-ldsm)
//   - GEMM1 C-fragment == GEMM2 A-fragment layout -> fused in registers
//   - only smem use: W1/W2 bf16 (ldmatrix B) + biases; NO barriers in loop
// ---------------------------------------------------------------------------

#define THREADS  128
#define WARPS    (THREADS / 32)
#define SSTRIDE  72   // bf16 elems per smem row (64 + 8 pad: conflict-free ldmatrix)

__device__ __forceinline__ uint32_t smem_u32(const void* p) {
    return (uint32_t)__cvta_generic_to_shared(p);
}

// pack (lo=v0, hi=v1) floats into bf16x2 register
__device__ __forceinline__ uint32_t packbf2(float v0, float v1) {
    uint32_t r;
    asm("cvt.rn.bf16x2.f32 %0, %1, %2;\n" : "=r"(r) : "f"(v1), "f"(v0));
    return r;
}

__device__ __forceinline__ void mma16816(float c[4], const uint32_t a[4],
                                         uint32_t b0, uint32_t b1) {
    asm volatile(
        "mma.sync.aligned.m16n8k16.row.col.f32.bf16.bf16.f32 "
        "{%0,%1,%2,%3}, {%4,%5,%6,%7}, {%8,%9}, {%0,%1,%2,%3};\n"
        : "+f"(c[0]), "+f"(c[1]), "+f"(c[2]), "+f"(c[3])
        : "r"(a[0]), "r"(a[1]), "r"(a[2]), "r"(a[3]), "r"(b0), "r"(b1));
}

__device__ __forceinline__ void ldsmB(uint32_t b[4], const __nv_bfloat16* base) {
    uint32_t addr = smem_u32(base);
    asm volatile("ldmatrix.sync.aligned.m8n8.x4.trans.shared.b16 {%0,%1,%2,%3}, [%4];\n"
                 : "=r"(b[0]), "=r"(b[1]), "=r"(b[2]), "=r"(b[3]) : "r"(addr));
}

struct Smem {
    __nv_bfloat16 W1[64 * SSTRIDE];
    __nv_bfloat16 W2[64 * SSTRIDE];
    float b1[64];
    float b2[64];
};

__device__ __forceinline__ float gaussv(float d, int c, float step, float coeff) {
    float t = d - (float)c * step;
    float v = __expf(coeff * t * t);
    return (c < 50) ? v : 0.0f;
}

__global__ void __launch_bounds__(THREADS)
lig_edge_kernel(const float* __restrict__ pos,
                const float* __restrict__ lig_ea,
                const void*  __restrict__ ei_raw,
                const float* __restrict__ W1g,
                const float* __restrict__ b1g,
                const float* __restrict__ W2g,
                const float* __restrict__ b2g,
                float* __restrict__ outAttr,
                int E, int numTiles)
{
    __shared__ Smem s;
    const int tid  = threadIdx.x;
    const int lane = tid & 31;
    const int warp = tid >> 5;
    const int g    = lane >> 2;      // row group 0..7
    const int t4   = lane & 3;       // col pair selector

    const long long* ei64 = (const long long*)ei_raw;
    const int*       ei32 = (const int*)ei_raw;

    // ---- edge_index dtype detection (per warp, once; cached loads) ----
    int idx64;
    {
        long long v = 0;
        if (lane < 16 && lane < E) v = ei64[lane];
        int ok = (v >= 0 && v < (1LL << 31));
        idx64 = __all_sync(0xffffffffu, ok) ? 1 : 0;
    }

    // ---- one-time weight staging (bf16; W1 K-rows 50..63 zeroed) ----
    for (int i = tid; i < 64 * 64; i += THREADS) {
        int r = i >> 6, c = i & 63;
        s.W1[r * SSTRIDE + c] = __float2bfloat16(r < 50 ? W1g[r * 64 + c] : 0.0f);
        s.W2[r * SSTRIDE + c] = __float2bfloat16(W2g[i]);
    }
    if (tid < 64) { s.b1[tid] = b1g[tid]; s.b2[tid] = b2g[tid]; }
    __syncthreads();   // only barrier in the kernel

    const float step  = 30.0f / 49.0f;
    const float coeff = -0.5f * (49.0f / 30.0f) * (49.0f / 30.0f);

    const int gwarp      = blockIdx.x * WARPS + warp;
    const int totalWarps = gridDim.x * WARPS;

    for (int tile = gwarp; tile < numTiles; tile += totalWarps) {
        const long long e0 = (long long)tile * 16;

        // ---- distances: lanes 0..15 load src endpoint, 16..31 load dst ----
        const int  el  = lane & 15;
        const long long e = e0 + el;
        const bool ve  = (e < E);
        long long nodeIdx = 0;
        if (ve) {
            long long pos_in_ei = (lane < 16) ? e : ((long long)E + e);
            nodeIdx = idx64 ? ei64[pos_in_ei] : (long long)ei32[pos_in_ei];
        }
        const float* P = pos + nodeIdx * 3;
        float x = P[0], y = P[1], z = P[2];
        float dx = __shfl_xor_sync(0xffffffffu, x, 16) - x;
        float dy = __shfl_xor_sync(0xffffffffu, y, 16) - y;
        float dz = __shfl_xor_sync(0xffffffffu, z, 16) - z;
        float d  = sqrtf(dx * dx + dy * dy + dz * dz);
        // d on lane L is for edge (L & 15); broadcast the two rows this lane owns
        const float dg  = __shfl_sync(0xffffffffu, d, g);
        const float dg8 = __shfl_sync(0xffffffffu, d, g + 8);

        // ---- GEMM1: acc1 = G @ W1 ; A built in registers from gaussians ----
        float acc1[8][4] = {};
#pragma unroll
        for (int kt = 0; kt < 4; kt++) {
            uint32_t a[4];
            const int c0 = kt * 16 + 2 * t4;
            a[0] = packbf2(gaussv(dg,  c0,     step, coeff),
                           gaussv(dg,  c0 + 1, step, coeff));
            a[1] = packbf2(gaussv(dg8, c0,     step, coeff),
                           gaussv(dg8, c0 + 1, step, coeff));
            a[2] = packbf2(gaussv(dg,  c0 + 8, step, coeff),
                           gaussv(dg,  c0 + 9, step, coeff));
            a[3] = packbf2(gaussv(dg8, c0 + 8, step, coeff),
                           gaussv(dg8, c0 + 9, step, coeff));
#pragma unroll
            for (int j = 0; j < 8; j += 2) {
                uint32_t b[4];
                ldsmB(b, s.W1 + (kt * 16 + (lane & 15)) * SSTRIDE
                              + j * 8 + ((lane >> 4) * 8));
                mma16816(acc1[j],     a, b[0], b[1]);
                mma16816(acc1[j + 1], a, b[2], b[3]);
            }
        }

        // ---- relu+bias; repack C-fragments as A-fragments for GEMM2 ----
        uint32_t h[4][4];
#pragma unroll
        for (int j = 0; j < 8; j++) {
            const int col = j * 8 + 2 * t4;
            const float bb0 = s.b1[col], bb1 = s.b1[col + 1];
            float v0 = fmaxf(acc1[j][0] + bb0, 0.0f);
            float v1 = fmaxf(acc1[j][1] + bb1, 0.0f);
            float v2 = fmaxf(acc1[j][2] + bb0, 0.0f);
            float v3 = fmaxf(acc1[j][3] + bb1, 0.0f);
            const int kc = j >> 1, hi = j & 1;
            h[kc][2 * hi]     = packbf2(v0, v1);
            h[kc][2 * hi + 1] = packbf2(v2, v3);
        }

        // ---- GEMM2: acc2 = H @ W2 (A from registers) ----
        float acc2[8][4] = {};
#pragma unroll
        for (int kc = 0; kc < 4; kc++) {
#pragma unroll
            for (int j = 0; j < 8; j += 2) {
                uint32_t b[4];
                ldsmB(b, s.W2 + (kc * 16 + (lane & 15)) * SSTRIDE
                              + j * 8 + ((lane >> 4) * 8));
                mma16816(acc2[j],     h[kc], b[0], b[1]);
                mma16816(acc2[j + 1], h[kc], b[2], b[3]);
            }
        }

        // ---- epilogue: out = lig_ea + emb + b2 ----
        const long long er0 = e0 + g;
        const long long er1 = e0 + g + 8;
#pragma unroll
        for (int j = 0; j < 8; j++) {
            const int col = j * 8 + 2 * t4;
            const float bb0 = s.b2[col], bb1 = s.b2[col + 1];
            if (er0 < E) {
                const float2 lg = *(const float2*)(lig_ea + er0 * 64 + col);
                float2 o; o.x = lg.x + acc2[j][0] + bb0; o.y = lg.y + acc2[j][1] + bb1;
                *(float2*)(outAttr + er0 * 64 + col) = o;
            }
            if (er1 < E) {
                const float2 lg = *(const float2*)(lig_ea + er1 * 64 + col);
                float2 o; o.x = lg.x + acc2[j][2] + bb0; o.y = lg.y + acc2[j][3] + bb1;
                *(float2*)(outAttr + er1 * 64 + col) = o;
            }
        }
    }
}

// ---- optional edge_index output paths (self-detecting dtype) -------------
__device__ __forceinline__ int detect64(const void* ei, int E) {
    const long long* p = (const long long*)ei;
    int ok = 1;
    int n = E < 16 ? E : 16;
    for (int i = 0; i < n; i++) {
        long long v = p[i];
        if (v < 0 || v >= (1LL << 31)) { ok = 0; break; }
    }
    return ok;
}

__global__ void write_idx_float(const void* __restrict__ ei, float* __restrict__ out,
                                int n, int E) {
    int i = blockIdx.x * blockDim.x + threadIdx.x;
    if (i < n) {
        int is64 = detect64(ei, E);
        long long v = is64 ? ((const long long*)ei)[i] : (long long)((const int*)ei)[i];
        out[i] = (float)v;
    }
}

__global__ void write_idx_raw(const void* __restrict__ ei, long long* __restrict__ out,
                              int n, int E) {
    int i = blockIdx.x * blockDim.x + threadIdx.x;
    if (i < n) {
        int is64 = detect64(ei, E);
        long long v = is64 ? ((const long long*)ei)[i] : (long long)((const int*)ei)[i];
        out[i] = v;
    }
}

extern "C" void kernel_launch(void* const* d_in, const int* in_sizes, int n_in,
                              void* d_out, int out_size)
{
    const float* pos = nullptr;
    const float* lig = nullptr;
    const void*  ei  = nullptr;
    const float* W1  = nullptr;
    const float* b1  = nullptr;
    const float* W2  = nullptr;
    const float* b2  = nullptr;

    long long maxSz = -1; int ligIdx = -1;
    for (int i = 0; i < n_in; i++)
        if ((long long)in_sizes[i] > maxSz) { maxSz = in_sizes[i]; ligIdx = i; }
    lig = (const float*)d_in[ligIdx];
    const int E = (int)(maxSz / 64);

    for (int i = 0; i < n_in; i++) {
        long long sz = in_sizes[i];
        if (i == ligIdx) continue;
        if (sz == 50LL * 64)          W1 = (const float*)d_in[i];
        else if (sz == 64LL * 64)     W2 = (const float*)d_in[i];
        else if (sz == 64) {
            if (!b1) b1 = (const float*)d_in[i];
            else     b2 = (const float*)d_in[i];
        }
        else if (sz == 2LL * E || sz == 4LL * E) ei = d_in[i];
        else                        pos = (const float*)d_in[i];
    }

    float* out  = (float*)d_out;
    float* attr = out;
    const long long nAttr = (long long)E * 64;

    if ((long long)out_size == nAttr + 2LL * E) {
        int n = 2 * E;
        write_idx_float<<<(n + 255) / 256, 256>>>(ei, out, n, E);
        attr = out + 2LL * E;
    } else if ((long long)out_size == nAttr + 4LL * E) {
        int n = 2 * E;
        write_idx_raw<<<(n + 255) / 256, 256>>>(ei, (long long*)d_out, n, E);
        attr = out + 4LL * E;
    }

    const int numTiles = (E + 15) / 16;
    int grid = (numTiles + WARPS - 1) / WARPS;
    if (grid > 1184) grid = 1184;   // 148 SMs * ~8 blocks, grid-stride persistent
    lig_edge_kernel<<<grid, THREADS>>>(pos, lig, ei, W1, b1, W2, b2, attr, E, numTiles);
}

// round 5
// speedup vs baseline: 1.2603x; 1.0306x over previous
#include <cuda_runtime.h>
#include <cuda_bf16.h>
#include <cstdint>

// ---------------------------------------------------------------------------
// LigEdgeBuilder: edge_attr = lig_ea + (relu(gauss(d) @ W1 + b1) @ W2 + b2)
// Warp-autonomous, fully register-resident weights:
//   - B fragments of W1/W2 ldmatrix'd ONCE into registers (128 regs), zero
//     smem/L1 traffic from weights inside the loop
//   - Gaussian A-fragments built in registers; GEMM1 C == GEMM2 A layout
//   - no barriers in loop; 2 CTAs/SM (reg-limited), persistent grid-stride
// ---------------------------------------------------------------------------

#define THREADS  128
#define WARPS    (THREADS / 32)
#define SSTRIDE  72   // bf16 elems per smem row (64 + 8 pad: conflict-free ldmatrix)

__device__ __forceinline__ uint32_t smem_u32(const void* p) {
    return (uint32_t)__cvta_generic_to_shared(p);
}

// pack (lo=v0, hi=v1) floats into bf16x2 register
__device__ __forceinline__ uint32_t packbf2(float v0, float v1) {
    uint32_t r;
    asm("cvt.rn.bf16x2.f32 %0, %1, %2;\n" : "=r"(r) : "f"(v1), "f"(v0));
    return r;
}

__device__ __forceinline__ void mma16816(float c[4], const uint32_t a[4],
                                         uint32_t b0, uint32_t b1) {
    asm volatile(
        "mma.sync.aligned.m16n8k16.row.col.f32.bf16.bf16.f32 "
        "{%0,%1,%2,%3}, {%4,%5,%6,%7}, {%8,%9}, {%0,%1,%2,%3};\n"
        : "+f"(c[0]), "+f"(c[1]), "+f"(c[2]), "+f"(c[3])
        : "r"(a[0]), "r"(a[1]), "r"(a[2]), "r"(a[3]), "r"(b0), "r"(b1));
}

__device__ __forceinline__ void ldsmB(uint32_t b[4], const __nv_bfloat16* base) {
    uint32_t addr = smem_u32(base);
    asm volatile("ldmatrix.sync.aligned.m8n8.x4.trans.shared.b16 {%0,%1,%2,%3}, [%4];\n"
                 : "=r"(b[0]), "=r"(b[1]), "=r"(b[2]), "=r"(b[3]) : "r"(addr));
}

struct Smem {
    __nv_bfloat16 W1[64 * SSTRIDE];
    __nv_bfloat16 W2[64 * SSTRIDE];
    float b1[64];
    float b2[64];
};

__device__ __forceinline__ float gaussv(float d, int c, float step, float coeff) {
    float t = d - (float)c * step;
    float v = 0.0f;
    if (c < 50 && fabsf(t) < 3.6f)     // tail < 3e-8: below bf16 resolution
        v = __expf(coeff * t * t);
    return v;
}

__global__ void __launch_bounds__(THREADS, 2)
lig_edge_kernel(const float* __restrict__ pos,
                const float* __restrict__ lig_ea,
                const void*  __restrict__ ei_raw,
                const float* __restrict__ W1g,
                const float* __restrict__ b1g,
                const float* __restrict__ W2g,
                const float* __restrict__ b2g,
                float* __restrict__ outAttr,
                int E, int numTiles)
{
    __shared__ Smem s;
    const int tid  = threadIdx.x;
    const int lane = tid & 31;
    const int warp = tid >> 5;
    const int g    = lane >> 2;      // row group 0..7
    const int t4   = lane & 3;       // col pair selector

    const long long* ei64 = (const long long*)ei_raw;
    const int*       ei32 = (const int*)ei_raw;

    // ---- edge_index dtype detection (per warp, once) ----
    int idx64;
    {
        long long v = 0;
        if (lane < 16 && lane < E) v = ei64[lane];
        int ok = (v >= 0 && v < (1LL << 31));
        idx64 = __all_sync(0xffffffffu, ok) ? 1 : 0;
    }

    // ---- one-time weight staging (bf16; W1 K-rows 50..63 zeroed) ----
    for (int i = tid; i < 64 * 64; i += THREADS) {
        int r = i >> 6, c = i & 63;
        s.W1[r * SSTRIDE + c] = __float2bfloat16(r < 50 ? W1g[r * 64 + c] : 0.0f);
        s.W2[r * SSTRIDE + c] = __float2bfloat16(W2g[i]);
    }
    if (tid < 64) { s.b1[tid] = b1g[tid]; s.b2[tid] = b2g[tid]; }
    __syncthreads();   // only barrier in the kernel

    // ---- hoist ALL B fragments into registers (loop-invariant) ----
    uint32_t B1[4][4][4];   // [kt][jp][frag]
    uint32_t B2[4][4][4];
#pragma unroll
    for (int kt = 0; kt < 4; kt++) {
#pragma unroll
        for (int jp = 0; jp < 4; jp++) {
            ldsmB(B1[kt][jp], s.W1 + (kt * 16 + (lane & 15)) * SSTRIDE
                                   + jp * 16 + ((lane >> 4) * 8));
            ldsmB(B2[kt][jp], s.W2 + (kt * 16 + (lane & 15)) * SSTRIDE
                                   + jp * 16 + ((lane >> 4) * 8));
        }
    }

    const float step  = 30.0f / 49.0f;
    const float coeff = -0.5f * (49.0f / 30.0f) * (49.0f / 30.0f);

    const int gwarp      = blockIdx.x * WARPS + warp;
    const int totalWarps = gridDim.x * WARPS;

    for (int tile = gwarp; tile < numTiles; tile += totalWarps) {
        const long long e0 = (long long)tile * 16;

        // ---- distances: lanes 0..15 load src endpoint, 16..31 load dst ----
        const int  el  = lane & 15;
        const long long e = e0 + el;
        long long nodeIdx = 0;
        if (e < E) {
            long long pos_in_ei = (lane < 16) ? e : ((long long)E + e);
            nodeIdx = idx64 ? ei64[pos_in_ei] : (long long)ei32[pos_in_ei];
        }
        const float* P = pos + nodeIdx * 3;
        float x = P[0], y = P[1], z = P[2];
        float dx = __shfl_xor_sync(0xffffffffu, x, 16) - x;
        float dy = __shfl_xor_sync(0xffffffffu, y, 16) - y;
        float dz = __shfl_xor_sync(0xffffffffu, z, 16) - z;
        float d  = sqrtf(dx * dx + dy * dy + dz * dz);
        const float dg  = __shfl_sync(0xffffffffu, d, g);
        const float dg8 = __shfl_sync(0xffffffffu, d, g + 8);

        // ---- GEMM1: acc1 = G @ W1 ; A built in registers from gaussians ----
        float acc1[8][4] = {};
#pragma unroll
        for (int kt = 0; kt < 4; kt++) {
            uint32_t a[4];
            const int c0 = kt * 16 + 2 * t4;
            a[0] = packbf2(gaussv(dg,  c0,     step, coeff),
                           gaussv(dg,  c0 + 1, step, coeff));
            a[1] = packbf2(gaussv(dg8, c0,     step, coeff),
                           gaussv(dg8, c0 + 1, step, coeff));
            a[2] = packbf2(gaussv(dg,  c0 + 8, step, coeff),
                           gaussv(dg,  c0 + 9, step, coeff));
            a[3] = packbf2(gaussv(dg8, c0 + 8, step, coeff),
                           gaussv(dg8, c0 + 9, step, coeff));
#pragma unroll
            for (int jp = 0; jp < 4; jp++) {
                mma16816(acc1[2 * jp],     a, B1[kt][jp][0], B1[kt][jp][1]);
                mma16816(acc1[2 * jp + 1], a, B1[kt][jp][2], B1[kt][jp][3]);
            }
        }

        // ---- relu+bias; repack C-fragments as A-fragments for GEMM2 ----
        uint32_t h[4][4];
#pragma unroll
        for (int j = 0; j < 8; j++) {
            const int col = j * 8 + 2 * t4;
            const float bb0 = s.b1[col], bb1 = s.b1[col + 1];
            float v0 = fmaxf(acc1[j][0] + bb0, 0.0f);
            float v1 = fmaxf(acc1[j][1] + bb1, 0.0f);
            float v2 = fmaxf(acc1[j][2] + bb0, 0.0f);
            float v3 = fmaxf(acc1[j][3] + bb1, 0.0f);
            const int kc = j >> 1, hi = j & 1;
            h[kc][2 * hi]     = packbf2(v0, v1);
            h[kc][2 * hi + 1] = packbf2(v2, v3);
        }

        // ---- GEMM2: acc2 = H @ W2 (A and B from registers) ----
        float acc2[8][4] = {};
#pragma unroll
        for (int kc = 0; kc < 4; kc++) {
#pragma unroll
            for (int jp = 0; jp < 4; jp++) {
                mma16816(acc2[2 * jp],     h[kc], B2[kc][jp][0], B2[kc][jp][1]);
                mma16816(acc2[2 * jp + 1], h[kc], B2[kc][jp][2], B2[kc][jp][3]);
            }
        }

        // ---- epilogue: out = lig_ea + emb + b2 ----
        const long long er0 = e0 + g;
        const long long er1 = e0 + g + 8;
#pragma unroll
        for (int j = 0; j < 8; j++) {
            const int col = j * 8 + 2 * t4;
            const float bb0 = s.b2[col], bb1 = s.b2[col + 1];
            if (er0 < E) {
                const float2 lg = *(const float2*)(lig_ea + er0 * 64 + col);
                float2 o; o.x = lg.x + acc2[j][0] + bb0; o.y = lg.y + acc2[j][1] + bb1;
                *(float2*)(outAttr + er0 * 64 + col) = o;
            }
            if (er1 < E) {
                const float2 lg = *(const float2*)(lig_ea + er1 * 64 + col);
                float2 o; o.x = lg.x + acc2[j][2] + bb0; o.y = lg.y + acc2[j][3] + bb1;
                *(float2*)(outAttr + er1 * 64 + col) = o;
            }
        }
    }
}

// ---- optional edge_index output paths (self-detecting dtype) -------------
__device__ __forceinline__ int detect64(const void* ei, int E) {
    const long long* p = (const long long*)ei;
    int ok = 1;
    int n = E < 16 ? E : 16;
    for (int i = 0; i < n; i++) {
        long long v = p[i];
        if (v < 0 || v >= (1LL << 31)) { ok = 0; break; }
    }
    return ok;
}

__global__ void write_idx_float(const void* __restrict__ ei, float* __restrict__ out,
                                int n, int E) {
    int i = blockIdx.x * blockDim.x + threadIdx.x;
    if (i < n) {
        int is64 = detect64(ei, E);
        long long v = is64 ? ((const long long*)ei)[i] : (long long)((const int*)ei)[i];
        out[i] = (float)v;
    }
}

__global__ void write_idx_raw(const void* __restrict__ ei, long long* __restrict__ out,
                              int n, int E) {
    int i = blockIdx.x * blockDim.x + threadIdx.x;
    if (i < n) {
        int is64 = detect64(ei, E);
        long long v = is64 ? ((const long long*)ei)[i] : (long long)((const int*)ei)[i];
        out[i] = v;
    }
}

extern "C" void kernel_launch(void* const* d_in, const int* in_sizes, int n_in,
                              void* d_out, int out_size)
{
    const float* pos = nullptr;
    const float* lig = nullptr;
    const void*  ei  = nullptr;
    const float* W1  = nullptr;
    const float* b1  = nullptr;
    const float* W2  = nullptr;
    const float* b2  = nullptr;

    long long maxSz = -1; int ligIdx = -1;
    for (int i = 0; i < n_in; i++)
        if ((long long)in_sizes[i] > maxSz) { maxSz = in_sizes[i]; ligIdx = i; }
    lig = (const float*)d_in[ligIdx];
    const int E = (int)(maxSz / 64);

    for (int i = 0; i < n_in; i++) {
        long long sz = in_sizes[i];
        if (i == ligIdx) continue;
        if (sz == 50LL * 64)          W1 = (const float*)d_in[i];
        else if (sz == 64LL * 64)     W2 = (const float*)d_in[i];
        else if (sz == 64) {
            if (!b1) b1 = (const float*)d_in[i];
            else     b2 = (const float*)d_in[i];
        }
        else if (sz == 2LL * E || sz == 4LL * E) ei = d_in[i];
        else                        pos = (const float*)d_in[i];
    }

    float* out  = (float*)d_out;
    float* attr = out;
    const long long nAttr = (long long)E * 64;

    if ((long long)out_size == nAttr + 2LL * E) {
        int n = 2 * E;
        write_idx_float<<<(n + 255) / 256, 256>>>(ei, out, n, E);
        attr = out + 2LL * E;
    } else if ((long long)out_size == nAttr + 4LL * E) {
        int n = 2 * E;
        write_idx_raw<<<(n + 255) / 256, 256>>>(ei, (long long*)d_out, n, E);
        attr = out + 4LL * E;
    }

    const int numTiles = (E + 15) / 16;
    int grid = (numTiles + WARPS - 1) / WARPS;
    if (grid > 296) grid = 296;   // 148 SMs * 2 resident CTAs (reg-limited)
    lig_edge_kernel<<<grid, THREADS>>>(pos, lig, ei, W1, b1, W2, b2, attr, E, numTiles);
}

// round 7
// speedup vs baseline: 1.5643x; 1.2412x over previous
#include <cuda_runtime.h>
#include <cuda_bf16.h>
#include <cstdint>

// ---------------------------------------------------------------------------
// LigEdgeBuilder: edge_attr = lig_ea + (relu(gauss(d) @ W1 + b1) @ W2 + b2)
// Warp-autonomous + fully software-pipelined:
//   - W1/W2 B-fragments register-resident (loaded once via ldmatrix)
//   - lig_ea tile prefetched 1 iteration ahead via cp.async.cg (double buffer)
//   - edge_index -> pos -> d chain pipelined 1 iteration ahead
//   - epilogue: LDS (padded, conflict-free) + streaming stores (__stcs)
// ---------------------------------------------------------------------------

#define THREADS    128
#define WARPS      (THREADS / 32)
#define SSTRIDE    72   // bf16 row stride for W tiles (conflict-free ldmatrix)
#define LIGSTRIDE  68   // float row stride for lig buffer (68%32=4 -> conflict-free)

__device__ __forceinline__ uint32_t smem_u32(const void* p) {
    return (uint32_t)__cvta_generic_to_shared(p);
}

__device__ __forceinline__ uint32_t packbf2(float v0, float v1) {
    uint32_t r;
    asm("cvt.rn.bf16x2.f32 %0, %1, %2;\n" : "=r"(r) : "f"(v1), "f"(v0));
    return r;
}

__device__ __forceinline__ void mma16816(float c[4], const uint32_t a[4],
                                         uint32_t b0, uint32_t b1) {
    asm volatile(
        "mma.sync.aligned.m16n8k16.row.col.f32.bf16.bf16.f32 "
        "{%0,%1,%2,%3}, {%4,%5,%6,%7}, {%8,%9}, {%0,%1,%2,%3};\n"
        : "+f"(c[0]), "+f"(c[1]), "+f"(c[2]), "+f"(c[3])
        : "r"(a[0]), "r"(a[1]), "r"(a[2]), "r"(a[3]), "r"(b0), "r"(b1));
}

__device__ __forceinline__ void ldsmB(uint32_t b[4], const __nv_bfloat16* base) {
    uint32_t addr = smem_u32(base);
    asm volatile("ldmatrix.sync.aligned.m8n8.x4.trans.shared.b16 {%0,%1,%2,%3}, [%4];\n"
                 : "=r"(b[0]), "=r"(b[1]), "=r"(b[2]), "=r"(b[3]) : "r"(addr));
}

struct Smem {
    __nv_bfloat16 W1[64 * SSTRIDE];
    __nv_bfloat16 W2[64 * SSTRIDE];
    float b1[64];
    float b2[64];
    float lig[WARPS][2][16 * LIGSTRIDE];   // double-buffered 16x64 tile per warp
};

__device__ __forceinline__ float gaussv(float d, int c, float step, float coeff) {
    float t = d - (float)c * step;
    float v = 0.0f;
    if (c < 50 && fabsf(t) < 3.6f)     // tail < 3e-8: below bf16 resolution
        v = __expf(coeff * t * t);
    return v;
}

// prefetch one 16x64-f32 lig tile (4KB) into smem via cp.async (register-free)
__device__ __forceinline__ void prefetchLig(const float* __restrict__ lig_ea,
                                            long long e0, int E,
                                            float* dstBase, int lane) {
    const char* base = (const char*)lig_ea;
#pragma unroll
    for (int k = 0; k < 8; k++) {
        int c     = k * 32 + lane;       // chunk 0..255, 16B each
        int row   = c >> 4;              // edge row 0..15
        int off16 = c & 15;              // 16B offset within row
        long long eRow = e0 + row;
        const char* src = (eRow < E) ? (base + (eRow * 256 + off16 * 16)) : base;
        uint32_t dst = smem_u32(dstBase + row * LIGSTRIDE) + off16 * 16;
        asm volatile("cp.async.cg.shared.global [%0], [%1], 16;\n"
                     :: "r"(dst), "l"(src));
    }
    asm volatile("cp.async.commit_group;\n" ::: "memory");
}

__global__ void __launch_bounds__(THREADS, 2)
lig_edge_kernel(const float* __restrict__ pos,
                const float* __restrict__ lig_ea,
                const void*  __restrict__ ei_raw,
                const float* __restrict__ W1g,
                const float* __restrict__ b1g,
                const float* __restrict__ W2g,
                const float* __restrict__ b2g,
                float* __restrict__ outAttr,
                int E, int numTiles)
{
    __shared__ Smem s;
    const int tid  = threadIdx.x;
    const int lane = tid & 31;
    const int warp = tid >> 5;
    const int g    = lane >> 2;
    const int t4   = lane & 3;

    const long long* ei64 = (const long long*)ei_raw;
    const int*       ei32 = (const int*)ei_raw;

    // ---- edge_index dtype detection (per warp, once) ----
    int idx64;
    {
        long long v = 0;
        if (lane < 16 && lane < E) v = ei64[lane];
        int ok = (v >= 0 && v < (1LL << 31));
        idx64 = __all_sync(0xffffffffu, ok) ? 1 : 0;
    }

    // ---- one-time weight staging (bf16; W1 K-rows 50..63 zeroed) ----
    for (int i = tid; i < 64 * 64; i += THREADS) {
        int r = i >> 6, c = i & 63;
        s.W1[r * SSTRIDE + c] = __float2bfloat16(r < 50 ? W1g[r * 64 + c] : 0.0f);
        s.W2[r * SSTRIDE + c] = __float2bfloat16(W2g[i]);
    }
    if (tid < 64) { s.b1[tid] = b1g[tid]; s.b2[tid] = b2g[tid]; }
    __syncthreads();   // only block barrier in the kernel

    // ---- hoist ALL B fragments into registers (loop-invariant) ----
    uint32_t B1[4][4][4];
    uint32_t B2[4][4][4];
#pragma unroll
    for (int kt = 0; kt < 4; kt++) {
#pragma unroll
        for (int jp = 0; jp < 4; jp++) {
            ldsmB(B1[kt][jp], s.W1 + (kt * 16 + (lane & 15)) * SSTRIDE
                                   + jp * 16 + ((lane >> 4) * 8));
            ldsmB(B2[kt][jp], s.W2 + (kt * 16 + (lane & 15)) * SSTRIDE
                                   + jp * 16 + ((lane >> 4) * 8));
        }
    }

    const float step  = 30.0f / 49.0f;
    const float coeff = -0.5f * (49.0f / 30.0f) * (49.0f / 30.0f);

    const int gwarp      = blockIdx.x * WARPS + warp;
    const int totalWarps = gridDim.x * WARPS;

    int tile = gwarp;
    int par  = 0;
    float dCur = 0.0f;

    if (tile < numTiles) {
        // ---- prime the pipeline: lig tile + distance for tile 0 ----
        prefetchLig(lig_ea, (long long)tile * 16, E, &s.lig[warp][0][0], lane);
        const int el = lane & 15;
        long long e = (long long)tile * 16 + el;
        long long nodeIdx = 0;
        if (e < E) {
            long long sel = (lane < 16) ? e : ((long long)E + e);
            nodeIdx = idx64 ? ei64[sel] : (long long)ei32[sel];
        }
        const float* P = pos + nodeIdx * 3;
        float x = P[0], y = P[1], z = P[2];
        float dx = __shfl_xor_sync(0xffffffffu, x, 16) - x;
        float dy = __shfl_xor_sync(0xffffffffu, y, 16) - y;
        float dz = __shfl_xor_sync(0xffffffffu, z, 16) - z;
        dCur = sqrtf(dx * dx + dy * dy + dz * dz);
    }

    for (; tile < numTiles; tile += totalWarps) {
        const long long e0 = (long long)tile * 16;
        const int nxt  = tile + totalWarps;
        const int nxtC = (nxt < numTiles) ? nxt : tile;   // clamped (dup harmless)

        // ---- issue next-iteration prefetches FIRST (overlap with GEMMs) ----
        prefetchLig(lig_ea, (long long)nxtC * 16, E, &s.lig[warp][par ^ 1][0], lane);

        long long eN = (long long)nxtC * 16 + (lane & 15);
        long long nodeIdxN = 0;
        if (eN < E) {
            long long sel = (lane < 16) ? eN : ((long long)E + eN);
            nodeIdxN = idx64 ? ei64[sel] : (long long)ei32[sel];
        }
        const float* PN = pos + nodeIdxN * 3;
        float xN = PN[0], yN = PN[1], zN = PN[2];

        const float dg  = __shfl_sync(0xffffffffu, dCur, g);
        const float dg8 = __shfl_sync(0xffffffffu, dCur, g + 8);

        // ---- GEMM1: acc1 = G @ W1 ; A built in registers from gaussians ----
        float acc1[8][4] = {};
#pragma unroll
        for (int kt = 0; kt < 4; kt++) {
            uint32_t a[4];
            const int c0 = kt * 16 + 2 * t4;
            a[0] = packbf2(gaussv(dg,  c0,     step, coeff),
                           gaussv(dg,  c0 + 1, step, coeff));
            a[1] = packbf2(gaussv(dg8, c0,     step, coeff),
                           gaussv(dg8, c0 + 1, step, coeff));
            a[2] = packbf2(gaussv(dg,  c0 + 8, step, coeff),
                           gaussv(dg,  c0 + 9, step, coeff));
            a[3] = packbf2(gaussv(dg8, c0 + 8, step, coeff),
                           gaussv(dg8, c0 + 9, step, coeff));
#pragma unroll
            for (int jp = 0; jp < 4; jp++) {
                mma16816(acc1[2 * jp],     a, B1[kt][jp][0], B1[kt][jp][1]);
                mma16816(acc1[2 * jp + 1], a, B1[kt][jp][2], B1[kt][jp][3]);
            }
        }

        // ---- relu+bias; repack C-fragments as A-fragments for GEMM2 ----
        uint32_t h[4][4];
#pragma unroll
        for (int j = 0; j < 8; j++) {
            const int col = j * 8 + 2 * t4;
            const float bb0 = s.b1[col], bb1 = s.b1[col + 1];
            float v0 = fmaxf(acc1[j][0] + bb0, 0.0f);
            float v1 = fmaxf(acc1[j][1] + bb1, 0.0f);
            float v2 = fmaxf(acc1[j][2] + bb0, 0.0f);
            float v3 = fmaxf(acc1[j][3] + bb1, 0.0f);
            const int kc = j >> 1, hi = j & 1;
            h[kc][2 * hi]     = packbf2(v0, v1);
            h[kc][2 * hi + 1] = packbf2(v2, v3);
        }

        // ---- GEMM2: acc2 = H @ W2 (A and B from registers) ----
        float acc2[8][4] = {};
#pragma unroll
        for (int kc = 0; kc < 4; kc++) {
#pragma unroll
            for (int jp = 0; jp < 4; jp++) {
                mma16816(acc2[2 * jp],     h[kc], B2[kc][jp][0], B2[kc][jp][1]);
                mma16816(acc2[2 * jp + 1], h[kc], B2[kc][jp][2], B2[kc][jp][3]);
            }
        }

        // ---- wait for THIS tile's lig prefetch (1 newer group in flight) ----
        asm volatile("cp.async.wait_group 1;\n" ::: "memory");
        __syncwarp();

        // ---- epilogue: out = lig(smem) + emb + b2, streaming stores ----
        const float* lb = &s.lig[warp][par][0];
        const long long er0 = e0 + g;
        const long long er1 = e0 + g + 8;
#pragma unroll
        for (int j = 0; j < 8; j++) {
            const int col = j * 8 + 2 * t4;
            const float bb0 = s.b2[col], bb1 = s.b2[col + 1];
            const float2 lg0 = *(const float2*)(lb + g * LIGSTRIDE + col);
            const float2 lg1 = *(const float2*)(lb + (g + 8) * LIGSTRIDE + col);
            if (er0 < E) {
                float2 o; o.x = lg0.x + acc2[j][0] + bb0; o.y = lg0.y + acc2[j][1] + bb1;
                __stcs((float2*)(outAttr + er0 * 64 + col), o);
            }
            if (er1 < E) {
                float2 o; o.x = lg1.x + acc2[j][2] + bb0; o.y = lg1.y + acc2[j][3] + bb1;
                __stcs((float2*)(outAttr + er1 * 64 + col), o);
            }
        }

        // ---- finish next tile's distance (loads issued at loop top) ----
        float dx = __shfl_xor_sync(0xffffffffu, xN, 16) - xN;
        float dy = __shfl_xor_sync(0xffffffffu, yN, 16) - yN;
        float dz = __shfl_xor_sync(0xffffffffu, zN, 16) - zN;
        dCur = sqrtf(dx * dx + dy * dy + dz * dz);
        par ^= 1;
    }
}

// ---- optional edge_index output paths (self-detecting dtype) -------------
__device__ __forceinline__ int detect64(const void* ei, int E) {
    const long long* p = (const long long*)ei;
    int ok = 1;
    int n = E < 16 ? E : 16;
    for (int i = 0; i < n; i++) {
        long long v = p[i];
        if (v < 0 || v >= (1LL << 31)) { ok = 0; break; }
    }
    return ok;
}

__global__ void write_idx_float(const void* __restrict__ ei, float* __restrict__ out,
                                int n, int E) {
    int i = blockIdx.x * blockDim.x + threadIdx.x;
    if (i < n) {
        int is64 = detect64(ei, E);
        long long v = is64 ? ((const long long*)ei)[i] : (long long)((const int*)ei)[i];
        out[i] = (float)v;
    }
}

__global__ void write_idx_raw(const void* __restrict__ ei, long long* __restrict__ out,
                              int n, int E) {
    int i = blockIdx.x * blockDim.x + threadIdx.x;
    if (i < n) {
        int is64 = detect64(ei, E);
        long long v = is64 ? ((const long long*)ei)[i] : (long long)((const int*)ei)[i];
        out[i] = v;
    }
}

extern "C" void kernel_launch(void* const* d_in, const int* in_sizes, int n_in,
                              void* d_out, int out_size)
{
    const float* pos = nullptr;
    const float* lig = nullptr;
    const void*  ei  = nullptr;
    const float* W1  = nullptr;
    const float* b1  = nullptr;
    const float* W2  = nullptr;
    const float* b2  = nullptr;

    long long maxSz = -1; int ligIdx = -1;
    for (int i = 0; i < n_in; i++)
        if ((long long)in_sizes[i] > maxSz) { maxSz = in_sizes[i]; ligIdx = i; }
    lig = (const float*)d_in[ligIdx];
    const int E = (int)(maxSz / 64);

    for (int i = 0; i < n_in; i++) {
        long long sz = in_sizes[i];
        if (i == ligIdx) continue;
        if (sz == 50LL * 64)          W1 = (const float*)d_in[i];
        else if (sz == 64LL * 64)     W2 = (const float*)d_in[i];
        else if (sz == 64) {
            if (!b1) b1 = (const float*)d_in[i];
            else     b2 = (const float*)d_in[i];
        }
        else if (sz == 2LL * E || sz == 4LL * E) ei = d_in[i];
        else                        pos = (const float*)d_in[i];
    }

    float* out  = (float*)d_out;
    float* attr = out;
    const long long nAttr = (long long)E * 64;

    if ((long long)out_size == nAttr + 2LL * E) {
        int n = 2 * E;
        write_idx_float<<<(n + 255) / 256, 256>>>(ei, out, n, E);
        attr = out + 2LL * E;
    } else if ((long long)out_size == nAttr + 4LL * E) {
        int n = 2 * E;
        write_idx_raw<<<(n + 255) / 256, 256>>>(ei, (long long*)d_out, n, E);
        attr = out + 4LL * E;
    }

    const int numTiles = (E + 15) / 16;
    int grid = (numTiles + WARPS - 1) / WARPS;
    if (grid > 296) grid = 296;   // 148 SMs * 2 resident CTAs (reg-limited)
    lig_edge_kernel<<<grid, THREADS>>>(pos, lig, ei, W1, b1, W2, b2, attr, E, numTiles);
}

// round 8
// speedup vs baseline: 1.7296x; 1.1057x over previous
#include <cuda_runtime.h>
#include <cuda_bf16.h>
#include <cstdint>

// ---------------------------------------------------------------------------
// LigEdgeBuilder: edge_attr = lig_ea + (relu(gauss(d) @ W1 + b1) @ W2 + b2)
// Warp-autonomous + software-pipelined, 3 CTAs/SM:
//   - W2 B-fragments register-resident; W1 via ldmatrix (hidden under gauss)
//   - lig_ea tile prefetched 1 iter ahead via cp.async.cg (double buffer)
//   - edge_index -> pos -> d chain pipelined 1 iteration ahead
//   - ALL indexing 32-bit (everything fits: E*64 = 205M < 2^31)
// ---------------------------------------------------------------------------

#define THREADS    128
#define WARPS      (THREADS / 32)
#define SSTRIDE    72   // bf16 row stride for W tiles (conflict-free ldmatrix)
#define LIGSTRIDE  68   // float row stride for lig buffer (conflict-free LDS)

__device__ __forceinline__ uint32_t smem_u32(const void* p) {
    return (uint32_t)__cvta_generic_to_shared(p);
}

__device__ __forceinline__ uint32_t packbf2(float v0, float v1) {
    uint32_t r;
    asm("cvt.rn.bf16x2.f32 %0, %1, %2;\n" : "=r"(r) : "f"(v1), "f"(v0));
    return r;
}

__device__ __forceinline__ void mma16816(float c[4], const uint32_t a[4],
                                         uint32_t b0, uint32_t b1) {
    asm volatile(
        "mma.sync.aligned.m16n8k16.row.col.f32.bf16.bf16.f32 "
        "{%0,%1,%2,%3}, {%4,%5,%6,%7}, {%8,%9}, {%0,%1,%2,%3};\n"
        : "+f"(c[0]), "+f"(c[1]), "+f"(c[2]), "+f"(c[3])
        : "r"(a[0]), "r"(a[1]), "r"(a[2]), "r"(a[3]), "r"(b0), "r"(b1));
}

__device__ __forceinline__ void ldsmB(uint32_t b[4], const __nv_bfloat16* base) {
    uint32_t addr = smem_u32(base);
    asm volatile("ldmatrix.sync.aligned.m8n8.x4.trans.shared.b16 {%0,%1,%2,%3}, [%4];\n"
                 : "=r"(b[0]), "=r"(b[1]), "=r"(b[2]), "=r"(b[3]) : "r"(addr));
}

struct Smem {
    __nv_bfloat16 W1[64 * SSTRIDE];
    __nv_bfloat16 W2[64 * SSTRIDE];
    float b1[64];
    float b2[64];
    float lig[WARPS][2][16 * LIGSTRIDE];   // double-buffered 16x64 tile per warp
};

__device__ __forceinline__ float gaussv(float d, int c, float step, float coeff) {
    float t = d - (float)c * step;
    float v = 0.0f;
    if (c < 50 && fabsf(t) < 3.6f)     // tail < 3e-8: below bf16 resolution
        v = __expf(coeff * t * t);
    return v;
}

// prefetch one 16x64-f32 lig tile (4KB) into smem via cp.async (register-free)
__device__ __forceinline__ void prefetchLig(const float* __restrict__ lig_ea,
                                            int e0, int E,
                                            float* dstBase, int lane) {
    const char* base = (const char*)lig_ea;
#pragma unroll
    for (int k = 0; k < 8; k++) {
        int c     = k * 32 + lane;       // chunk 0..255, 16B each
        int row   = c >> 4;              // edge row 0..15
        int off16 = c & 15;              // 16B offset within row
        int eRow  = e0 + row;
        // byte offset fits int32: E*256 <= ~1.7G?  E=3.2M -> 819MB, OK
        const char* src = (eRow < E) ? (base + ((unsigned)eRow * 256u + off16 * 16)) : base;
        uint32_t dst = smem_u32(dstBase + row * LIGSTRIDE) + off16 * 16;
        asm volatile("cp.async.cg.shared.global [%0], [%1], 16;\n"
                     :: "r"(dst), "l"(src));
    }
    asm volatile("cp.async.commit_group;\n" ::: "memory");
}

__global__ void __launch_bounds__(THREADS, 3)
lig_edge_kernel(const float* __restrict__ pos,
                const float* __restrict__ lig_ea,
                const void*  __restrict__ ei_raw,
                const float* __restrict__ W1g,
                const float* __restrict__ b1g,
                const float* __restrict__ W2g,
                const float* __restrict__ b2g,
                float* __restrict__ outAttr,
                int E, int numTiles)
{
    __shared__ Smem s;
    const int tid  = threadIdx.x;
    const int lane = tid & 31;
    const int warp = tid >> 5;
    const int g    = lane >> 2;
    const int t4   = lane & 3;

    const long long* ei64 = (const long long*)ei_raw;
    const int*       ei32 = (const int*)ei_raw;

    // ---- edge_index dtype detection (per warp, once) ----
    int idx64;
    {
        long long v = 0;
        if (lane < 16 && lane < E) v = ei64[lane];
        int ok = (v >= 0 && v < (1LL << 31));
        idx64 = __all_sync(0xffffffffu, ok) ? 1 : 0;
    }

    // ---- one-time weight staging (bf16; W1 K-rows 50..63 zeroed) ----
    for (int i = tid; i < 64 * 64; i += THREADS) {
        int r = i >> 6, c = i & 63;
        s.W1[r * SSTRIDE + c] = __float2bfloat16(r < 50 ? W1g[r * 64 + c] : 0.0f);
        s.W2[r * SSTRIDE + c] = __float2bfloat16(W2g[i]);
    }
    if (tid < 64) { s.b1[tid] = b1g[tid]; s.b2[tid] = b2g[tid]; }
    __syncthreads();   // only block barrier in the kernel

    // ---- hoist W2 B-fragments into registers (needed right after repack) ----
    uint32_t B2[4][4][4];
#pragma unroll
    for (int kt = 0; kt < 4; kt++) {
#pragma unroll
        for (int jp = 0; jp < 4; jp++) {
            ldsmB(B2[kt][jp], s.W2 + (kt * 16 + (lane & 15)) * SSTRIDE
                                   + jp * 16 + ((lane >> 4) * 8));
        }
    }
    // W1 base address for in-loop ldmatrix (latency hidden under gauss/MUFU)
    const __nv_bfloat16* w1base = s.W1 + (lane & 15) * SSTRIDE + ((lane >> 4) * 8);

    const float step  = 30.0f / 49.0f;
    const float coeff = -0.5f * (49.0f / 30.0f) * (49.0f / 30.0f);

    const int gwarp      = blockIdx.x * WARPS + warp;
    const int totalWarps = gridDim.x * WARPS;

    int tile = gwarp;
    int par  = 0;
    float dCur = 0.0f;

    if (tile < numTiles) {
        // ---- prime the pipeline: lig tile + distance for tile 0 ----
        prefetchLig(lig_ea, tile * 16, E, &s.lig[warp][0][0], lane);
        int e = tile * 16 + (lane & 15);
        int nodeIdx = 0;
        if (e < E) {
            int sel = (lane < 16) ? e : (E + e);
            nodeIdx = idx64 ? (int)ei64[sel] : ei32[sel];
        }
        const float* P = pos + nodeIdx * 3;
        float x = P[0], y = P[1], z = P[2];
        float dx = __shfl_xor_sync(0xffffffffu, x, 16) - x;
        float dy = __shfl_xor_sync(0xffffffffu, y, 16) - y;
        float dz = __shfl_xor_sync(0xffffffffu, z, 16) - z;
        dCur = sqrtf(dx * dx + dy * dy + dz * dz);
    }

    for (; tile < numTiles; tile += totalWarps) {
        const int e0 = tile * 16;
        const int nxt  = tile + totalWarps;
        const int nxtC = (nxt < numTiles) ? nxt : tile;   // clamped (dup harmless)

        // ---- issue next-iteration prefetches FIRST (overlap with GEMMs) ----
        prefetchLig(lig_ea, nxtC * 16, E, &s.lig[warp][par ^ 1][0], lane);

        int eN = nxtC * 16 + (lane & 15);
        int nodeIdxN = 0;
        if (eN < E) {
            int sel = (lane < 16) ? eN : (E + eN);
            nodeIdxN = idx64 ? (int)ei64[sel] : ei32[sel];
        }
        const float* PN = pos + nodeIdxN * 3;
        float xN = PN[0], yN = PN[1], zN = PN[2];

        const float dg  = __shfl_sync(0xffffffffu, dCur, g);
        const float dg8 = __shfl_sync(0xffffffffu, dCur, g + 8);

        // ---- GEMM1: acc1 = G @ W1 ; A from gaussians, B via ldmatrix ----
        float acc1[8][4] = {};
#pragma unroll
        for (int kt = 0; kt < 4; kt++) {
            // issue B loads first so LDSM latency overlaps gauss computation
            uint32_t b[4][4];
#pragma unroll
            for (int jp = 0; jp < 4; jp++)
                ldsmB(b[jp], w1base + (kt * 16) * SSTRIDE + jp * 16);

            uint32_t a[4];
            const int c0 = kt * 16 + 2 * t4;
            a[0] = packbf2(gaussv(dg,  c0,     step, coeff),
                           gaussv(dg,  c0 + 1, step, coeff));
            a[1] = packbf2(gaussv(dg8, c0,     step, coeff),
                           gaussv(dg8, c0 + 1, step, coeff));
            a[2] = packbf2(gaussv(dg,  c0 + 8, step, coeff),
                           gaussv(dg,  c0 + 9, step, coeff));
            a[3] = packbf2(gaussv(dg8, c0 + 8, step, coeff),
                           gaussv(dg8, c0 + 9, step, coeff));
#pragma unroll
            for (int jp = 0; jp < 4; jp++) {
                mma16816(acc1[2 * jp],     a, b[jp][0], b[jp][1]);
                mma16816(acc1[2 * jp + 1], a, b[jp][2], b[jp][3]);
            }
        }

        // ---- relu+bias; repack C-fragments as A-fragments for GEMM2 ----
        uint32_t h[4][4];
#pragma unroll
        for (int j = 0; j < 8; j++) {
            const int col = j * 8 + 2 * t4;
            const float bb0 = s.b1[col], bb1 = s.b1[col + 1];
            float v0 = fmaxf(acc1[j][0] + bb0, 0.0f);
            float v1 = fmaxf(acc1[j][1] + bb1, 0.0f);
            float v2 = fmaxf(acc1[j][2] + bb0, 0.0f);
            float v3 = fmaxf(acc1[j][3] + bb1, 0.0f);
            const int kc = j >> 1, hi = j & 1;
            h[kc][2 * hi]     = packbf2(v0, v1);
            h[kc][2 * hi + 1] = packbf2(v2, v3);
        }

        // ---- GEMM2: acc2 = H @ W2 (A and B from registers) ----
        float acc2[8][4] = {};
#pragma unroll
        for (int kc = 0; kc < 4; kc++) {
#pragma unroll
            for (int jp = 0; jp < 4; jp++) {
                mma16816(acc2[2 * jp],     h[kc], B2[kc][jp][0], B2[kc][jp][1]);
                mma16816(acc2[2 * jp + 1], h[kc], B2[kc][jp][2], B2[kc][jp][3]);
            }
        }

        // ---- wait for THIS tile's lig prefetch (1 newer group in flight) ----
        asm volatile("cp.async.wait_group 1;\n" ::: "memory");
        __syncwarp();

        // ---- epilogue: out = lig(smem) + emb + b2, streaming stores ----
        const float* lb = &s.lig[warp][par][0];
        const int er0 = e0 + g;
        const int er1 = e0 + g + 8;
        float* out0 = outAttr + (unsigned)er0 * 64u;
        float* out1 = outAttr + (unsigned)er1 * 64u;
#pragma unroll
        for (int j = 0; j < 8; j++) {
            const int col = j * 8 + 2 * t4;
            const float bb0 = s.b2[col], bb1 = s.b2[col + 1];
            const float2 lg0 = *(const float2*)(lb + g * LIGSTRIDE + col);
            const float2 lg1 = *(const float2*)(lb + (g + 8) * LIGSTRIDE + col);
            if (er0 < E) {
                float2 o; o.x = lg0.x + acc2[j][0] + bb0; o.y = lg0.y + acc2[j][1] + bb1;
                __stcs((float2*)(out0 + col), o);
            }
            if (er1 < E) {
                float2 o; o.x = lg1.x + acc2[j][2] + bb0; o.y = lg1.y + acc2[j][3] + bb1;
                __stcs((float2*)(out1 + col), o);
            }
        }

        // ---- finish next tile's distance (loads issued at loop top) ----
        float dx = __shfl_xor_sync(0xffffffffu, xN, 16) - xN;
        float dy = __shfl_xor_sync(0xffffffffu, yN, 16) - yN;
        float dz = __shfl_xor_sync(0xffffffffu, zN, 16) - zN;
        dCur = sqrtf(dx * dx + dy * dy + dz * dz);
        par ^= 1;
    }
}

// ---- optional edge_index output paths (self-detecting dtype) -------------
__device__ __forceinline__ int detect64(const void* ei, int E) {
    const long long* p = (const long long*)ei;
    int ok = 1;
    int n = E < 16 ? E : 16;
    for (int i = 0; i < n; i++) {
        long long v = p[i];
        if (v < 0 || v >= (1LL << 31)) { ok = 0; break; }
    }
    return ok;
}

__global__ void write_idx_float(const void* __restrict__ ei, float* __restrict__ out,
                                int n, int E) {
    int i = blockIdx.x * blockDim.x + threadIdx.x;
    if (i < n) {
        int is64 = detect64(ei, E);
        long long v = is64 ? ((const long long*)ei)[i] : (long long)((const int*)ei)[i];
        out[i] = (float)v;
    }
}

__global__ void write_idx_raw(const void* __restrict__ ei, long long* __restrict__ out,
                              int n, int E) {
    int i = blockIdx.x * blockDim.x + threadIdx.x;
    if (i < n) {
        int is64 = detect64(ei, E);
        long long v = is64 ? ((const long long*)ei)[i] : (long long)((const int*)ei)[i];
        out[i] = v;
    }
}

extern "C" void kernel_launch(void* const* d_in, const int* in_sizes, int n_in,
                              void* d_out, int out_size)
{
    const float* pos = nullptr;
    const float* lig = nullptr;
    const void*  ei  = nullptr;
    const float* W1  = nullptr;
    const float* b1  = nullptr;
    const float* W2  = nullptr;
    const float* b2  = nullptr;

    long long maxSz = -1; int ligIdx = -1;
    for (int i = 0; i < n_in; i++)
        if ((long long)in_sizes[i] > maxSz) { maxSz = in_sizes[i]; ligIdx = i; }
    lig = (const float*)d_in[ligIdx];
    const int E = (int)(maxSz / 64);

    for (int i = 0; i < n_in; i++) {
        long long sz = in_sizes[i];
        if (i == ligIdx) continue;
        if (sz == 50LL * 64)          W1 = (const float*)d_in[i];
        else if (sz == 64LL * 64)     W2 = (const float*)d_in[i];
        else if (sz == 64) {
            if (!b1) b1 = (const float*)d_in[i];
            else     b2 = (const float*)d_in[i];
        }
        else if (sz == 2LL * E || sz == 4LL * E) ei = d_in[i];
        else                        pos = (const float*)d_in[i];
    }

    float* out  = (float*)d_out;
    float* attr = out;
    const long long nAttr = (long long)E * 64;

    if ((long long)out_size == nAttr + 2LL * E) {
        int n = 2 * E;
        write_idx_float<<<(n + 255) / 256, 256>>>(ei, out, n, E);
        attr = out + 2LL * E;
    } else if ((long long)out_size == nAttr + 4LL * E) {
        int n = 2 * E;
        write_idx_raw<<<(n + 255) / 256, 256>>>(ei, (long long*)d_out, n, E);
        attr = out + 4LL * E;
    }

    const int numTiles = (E + 15) / 16;
    int grid = (numTiles + WARPS - 1) / WARPS;
    if (grid > 444) grid = 444;   // 148 SMs * 3 resident CTAs
    lig_edge_kernel<<<grid, THREADS>>>(pos, lig, ei, W1, b1, W2, b2, attr, E, numTiles);
}